// round 1
// baseline (speedup 1.0000x reference)
#include <cuda_runtime.h>

#define NB 4096
#define ND 768
#define NF 12288
#define NC 256
#define NK 64

// ---------------- device scratch (static, no allocation) ----------------
__device__ float g_xc[NB * ND];                 // x_up - b_dec_up
__device__ float g_act[(size_t)NB * NF];        // pre_up, then approx (reused)
__device__ float g_WduT[(size_t)NF * ND];       // W_dec_up transposed  [F_up, D]
__device__ float g_WddT[(size_t)NF * ND];       // W_dec_down transposed [F_down, D]
__device__ float g_vw[NF * NC];                 // sampled virtual weights
__device__ float g_cvu[NF];                     // W_enc_down @ b_dec_up
__device__ float g_cvd[NF];                     // W_enc_down @ b_dec_down
__device__ int   g_upi[NB * NK];
__device__ float g_upv[NB * NK];
__device__ int   g_dni[NB * NK];
__device__ float g_dnv[NB * NK];
__device__ int   g_conn[NF * NC];               // int32 connections (-1 = dup)
__device__ int   g_flag;                        // 1 => raw connections are int32
__device__ int   g_counts[NF];
__device__ int   g_offs[NF + 1];
__device__ int   g_cursor[NF];
__device__ int   g_invr[NF * NC];               // inverted lists: j -> r
__device__ float g_invw[NF * NC];               // inverted lists: j -> vw value

// ---------------- small helpers ----------------
__device__ __forceinline__ unsigned fkey(float x) {
    unsigned u = __float_as_uint(x);
    return (u & 0x80000000u) ? ~u : (u | 0x80000000u);  // monotone map
}

// ---------------- setup kernels ----------------
__global__ void k_init() {
    int i = blockIdx.x * 256 + threadIdx.x;
    if (i < NF) { g_counts[i] = 0; g_cursor[i] = 0; }
    if (i == 0) g_flag = 0;
}

// Probe odd 32-bit words of the first half of connections: all zero => int64.
__global__ void k_detect(const unsigned* __restrict__ raw) {
    int i = blockIdx.x * 256 + threadIdx.x;  // i < NF*NC/2
    bool nz = (raw[2 * i + 1] != 0u);
    if (__syncthreads_or(nz) && threadIdx.x == 0) atomicOr(&g_flag, 1);
}

__global__ void k_conv(const int* __restrict__ raw) {
    int i = blockIdx.x * 256 + threadIdx.x;  // i < NF*NC
    int v = g_flag ? raw[i] : raw[2 * i];    // int32 direct, or low word of int64
    g_conn[i] = v;
}

// Remove duplicate connections within a row (reference mask is a set).
__global__ void k_dedup() {
    __shared__ int sj[NC];
    int r = blockIdx.x, c = threadIdx.x;
    int j = g_conn[r * NC + c];
    sj[c] = j;
    __syncthreads();
    bool dup = false;
    for (int cc = 0; cc < c; cc++) if (sj[cc] == j) { dup = true; break; }
    if (dup) g_conn[r * NC + c] = -1;
}

__global__ void k_prep_xc(const float* __restrict__ x_up, const float* __restrict__ bdu) {
    int i = blockIdx.x * 256 + threadIdx.x;  // i < NB*ND
    g_xc[i] = x_up[i] - bdu[i % ND];
}

__global__ void k_cvec(const float* __restrict__ Wed, const float* __restrict__ bdu,
                       const float* __restrict__ bdd) {
    int r = blockIdx.x * 8 + (threadIdx.x >> 5);
    int lane = threadIdx.x & 31;
    const float* wr = Wed + (size_t)r * ND;
    float s1 = 0.f, s2 = 0.f;
    for (int d = lane; d < ND; d += 32) { float w = wr[d]; s1 += w * bdu[d]; s2 += w * bdd[d]; }
    for (int o = 16; o; o >>= 1) { s1 += __shfl_xor_sync(~0u, s1, o); s2 += __shfl_xor_sync(~0u, s2, o); }
    if (!lane) { g_cvu[r] = s1; g_cvd[r] = s2; }
}

// in[rows][cols] -> out[cols][rows]
__global__ void k_transpose(const float* __restrict__ in, float* __restrict__ out,
                            int rows, int cols) {
    __shared__ float tile[32][33];
    int c0 = blockIdx.x * 32, r0 = blockIdx.y * 32;
    int x = threadIdx.x, y = threadIdx.y;  // (32, 8)
    for (int i = 0; i < 32; i += 8)
        tile[y + i][x] = in[(size_t)(r0 + y + i) * cols + c0 + x];
    __syncthreads();
    for (int i = 0; i < 32; i += 8)
        out[(size_t)(c0 + y + i) * rows + r0 + x] = tile[x][y + i];
}

// ---------------- fp32 SGEMM (NT: A[M,K] row-major, B[N,K] row-major) ----------------
#define BM 128
#define BN 128
#define BK 8
template <bool RELU>
__global__ __launch_bounds__(256, 2)
void k_sgemm(const float* __restrict__ A, const float* __restrict__ Bm,
             const float* __restrict__ bias, float* __restrict__ Co,
             int M, int N, int Kd) {
    __shared__ float As[BK][BM];
    __shared__ float Bs[BK][BN];
    int tid = threadIdx.x;
    int tx = tid & 15, ty = tid >> 4;
    int bm = blockIdx.y * BM, bn = blockIdx.x * BN;
    float acc[8][8];
#pragma unroll
    for (int i = 0; i < 8; i++)
#pragma unroll
        for (int j = 0; j < 8; j++) acc[i][j] = 0.f;

    int lr = tid >> 1;
    int lk = (tid & 1) * 4;
    const float* Ap = A + (size_t)(bm + lr) * Kd + lk;
    const float* Bp = Bm + (size_t)(bn + lr) * Kd + lk;

    for (int k0 = 0; k0 < Kd; k0 += BK) {
        float4 av = *(const float4*)(Ap + k0);
        float4 bv = *(const float4*)(Bp + k0);
        __syncthreads();
        As[lk + 0][lr] = av.x; As[lk + 1][lr] = av.y; As[lk + 2][lr] = av.z; As[lk + 3][lr] = av.w;
        Bs[lk + 0][lr] = bv.x; Bs[lk + 1][lr] = bv.y; Bs[lk + 2][lr] = bv.z; Bs[lk + 3][lr] = bv.w;
        __syncthreads();
#pragma unroll
        for (int kk = 0; kk < BK; kk++) {
            float ra[8], rb[8];
            *(float4*)&ra[0] = *(const float4*)&As[kk][ty * 8];
            *(float4*)&ra[4] = *(const float4*)&As[kk][ty * 8 + 4];
            *(float4*)&rb[0] = *(const float4*)&Bs[kk][tx * 8];
            *(float4*)&rb[4] = *(const float4*)&Bs[kk][tx * 8 + 4];
#pragma unroll
            for (int i = 0; i < 8; i++)
#pragma unroll
                for (int j = 0; j < 8; j++) acc[i][j] += ra[i] * rb[j];
        }
    }
    float bb[8];
#pragma unroll
    for (int j = 0; j < 8; j++) bb[j] = bias ? bias[bn + tx * 8 + j] : 0.f;
#pragma unroll
    for (int i = 0; i < 8; i++) {
        float* crow = Co + (size_t)(bm + ty * 8 + i) * N + bn + tx * 8;
        float4 v0, v1;
        float t[8];
#pragma unroll
        for (int j = 0; j < 8; j++) {
            float v = acc[i][j] + bb[j];
            if (RELU) v = fmaxf(v, 0.f);
            t[j] = v;
        }
        v0 = make_float4(t[0], t[1], t[2], t[3]);
        v1 = make_float4(t[4], t[5], t[6], t[7]);
        *(float4*)crow = v0;
        *(float4*)(crow + 4) = v1;
    }
}

// ---------------- exact top-64 via 4-level radix select ----------------
__global__ __launch_bounds__(256)
void k_topk(const float* __restrict__ mat, int* __restrict__ oidx, float* __restrict__ oval) {
    extern __shared__ unsigned char smraw[];
    float* vals = (float*)smraw;                       // NF floats
    int* hist = (int*)(smraw + (size_t)NF * 4);        // 256 ints
    __shared__ int sh_bin, sh_above, sh_ca, sh_ce;
    int b = blockIdx.x;
    const float* row = mat + (size_t)b * NF;
    for (int i = threadIdx.x; i < NF; i += 256) vals[i] = row[i];
    __syncthreads();

    unsigned prefix = 0;
    int need = NK, tot_above = 0;
    for (int lev = 0; lev < 4; lev++) {
        int shift = 24 - 8 * lev;
        for (int i = threadIdx.x; i < 256; i += 256) hist[i] = 0;
        __syncthreads();
        for (int i = threadIdx.x; i < NF; i += 256) {
            unsigned k = fkey(vals[i]);
            if (lev == 0 || (k >> (shift + 8)) == prefix)
                atomicAdd(&hist[(k >> shift) & 255], 1);
        }
        __syncthreads();
        if (threadIdx.x == 0) {
            int acc = 0, bb = 255;
            for (;;) { acc += hist[bb]; if (acc >= need || bb == 0) break; bb--; }
            sh_bin = bb;
            sh_above = acc - hist[bb];
        }
        __syncthreads();
        prefix = (prefix << 8) | (unsigned)sh_bin;
        need -= sh_above;
        tot_above += sh_above;
        __syncthreads();
    }
    if (threadIdx.x == 0) { sh_ca = 0; sh_ce = 0; }
    __syncthreads();
    unsigned Kstar = prefix;
    for (int i = threadIdx.x; i < NF; i += 256) {
        unsigned k = fkey(vals[i]);
        if (k > Kstar) {
            int p = atomicAdd(&sh_ca, 1);
            oidx[b * NK + p] = i; oval[b * NK + p] = vals[i];
        } else if (k == Kstar) {
            int p = atomicAdd(&sh_ce, 1);
            if (p < need) { oidx[b * NK + tot_above + p] = i; oval[b * NK + tot_above + p] = vals[i]; }
        }
    }
}

// ---------------- sampled virtual weights ----------------
__global__ __launch_bounds__(256)
void k_vw(const float* __restrict__ Wed) {
    __shared__ float arow[ND];
    int r = blockIdx.x;
    for (int d = threadIdx.x; d < ND; d += 256) arow[d] = Wed[(size_t)r * ND + d];
    __syncthreads();
    int warp = threadIdx.x >> 5, lane = threadIdx.x & 31;
    for (int c = warp; c < NC; c += 8) {
        int j = g_conn[r * NC + c];
        float s = 0.f;
        if (j >= 0) {
            const float* wr = g_WduT + (size_t)j * ND;
            for (int d = lane; d < ND; d += 32) s += arow[d] * wr[d];
        }
        for (int o = 16; o; o >>= 1) s += __shfl_xor_sync(~0u, s, o);
        if (!lane) g_vw[r * NC + c] = s;
    }
}

// ---------------- inverted connection index ----------------
__global__ void k_hist() {
    int i = blockIdx.x * 256 + threadIdx.x;
    int j = g_conn[i];
    if (j >= 0) atomicAdd(&g_counts[j], 1);
}

__global__ void k_scan() {  // single block, 1024 threads, 12 bins each
    __shared__ int part[1024];
    int t = threadIdx.x;
    int base = t * 12;
    int loc[12], s = 0;
    for (int i = 0; i < 12; i++) { loc[i] = s; s += g_counts[base + i]; }
    part[t] = s;
    __syncthreads();
    for (int o = 1; o < 1024; o <<= 1) {
        int v = (t >= o) ? part[t - o] : 0;
        __syncthreads();
        part[t] += v;
        __syncthreads();
    }
    int excl = part[t] - s;
    for (int i = 0; i < 12; i++) g_offs[base + i] = excl + loc[i];
    if (t == 1023) g_offs[NF] = part[1023];
}

__global__ void k_fill() {
    int i = blockIdx.x * 256 + threadIdx.x;
    int j = g_conn[i];
    if (j >= 0) {
        int p = atomicAdd(&g_cursor[j], 1);
        int e = g_offs[j] + p;
        g_invr[e] = i >> 8;   // r = i / NC
        g_invw[e] = g_vw[i];
    }
}

// ---------------- scatter contributions + finalize approx ----------------
__global__ __launch_bounds__(256)
void k_scatter(const float* __restrict__ lnscale, const float* __restrict__ bencd) {
    extern __shared__ float contrib[];  // NF floats
    int b = blockIdx.x;
    for (int i = threadIdx.x; i < NF; i += 256) contrib[i] = 0.f;
    __syncthreads();
    int warp = threadIdx.x >> 5, lane = threadIdx.x & 31;
    for (int t = warp; t < NK; t += 8) {
        float v = g_upv[b * NK + t];
        int j = g_upi[b * NK + t];
        if (v != 0.f) {
            int e0 = g_offs[j], e1 = g_offs[j + 1];
            for (int e = e0 + lane; e < e1; e += 32)
                atomicAdd(&contrib[g_invr[e]], v * g_invw[e]);
        }
    }
    __syncthreads();
    float ls = lnscale[b];
    float* arow = g_act + (size_t)b * NF;
    for (int i = threadIdx.x; i < NF; i += 256) {
        float val = __fdiv_rn(arow[i] + contrib[i] + g_cvu[i], ls) + bencd[i] - g_cvd[i];
        arow[i] = val;
    }
}

// ---------------- sparse decode ----------------
__global__ __launch_bounds__(256)
void k_decode(const float* __restrict__ bdd, float* __restrict__ out) {
    __shared__ int sj[NK];
    __shared__ float sv[NK];
    int b = blockIdx.x;
    if (threadIdx.x < NK) {
        sj[threadIdx.x] = g_dni[b * NK + threadIdx.x];
        sv[threadIdx.x] = g_dnv[b * NK + threadIdx.x];
    }
    __syncthreads();
    for (int d = threadIdx.x; d < ND; d += 256) {
        float acc = bdd[d];
        for (int t = 0; t < NK; t++)
            acc += sv[t] * g_WddT[(size_t)sj[t] * ND + d];
        out[(size_t)b * ND + d] = acc;
    }
}

// ---------------- launch ----------------
extern "C" void kernel_launch(void* const* d_in, const int* in_sizes, int n_in,
                              void* d_out, int out_size) {
    const float* initial_acts = (const float*)d_in[0];
    const float* x_up        = (const float*)d_in[1];
    const float* ln_scale    = (const float*)d_in[2];
    const float* W_enc_up    = (const float*)d_in[3];
    const float* b_enc_up    = (const float*)d_in[4];
    const float* b_dec_up    = (const float*)d_in[5];
    const float* W_dec_up    = (const float*)d_in[6];
    const float* W_enc_down  = (const float*)d_in[7];
    const float* b_enc_down  = (const float*)d_in[8];
    const float* b_dec_down  = (const float*)d_in[9];
    const float* W_dec_down  = (const float*)d_in[10];
    const void*  conn_raw    = d_in[11];

    void *pa, *pxc, *pWduT, *pWddT, *pui, *puv, *pdi, *pdv;
    cudaGetSymbolAddress(&pa, g_act);
    cudaGetSymbolAddress(&pxc, g_xc);
    cudaGetSymbolAddress(&pWduT, g_WduT);
    cudaGetSymbolAddress(&pWddT, g_WddT);
    cudaGetSymbolAddress(&pui, g_upi);
    cudaGetSymbolAddress(&puv, g_upv);
    cudaGetSymbolAddress(&pdi, g_dni);
    cudaGetSymbolAddress(&pdv, g_dnv);
    float* act = (float*)pa;
    float* xc = (float*)pxc;

    const int topk_smem = NF * 4 + 256 * 4;       // 50176
    const int scat_smem = NF * 4;                 // 49152
    cudaFuncSetAttribute(k_topk, cudaFuncAttributeMaxDynamicSharedMemorySize, topk_smem);
    cudaFuncSetAttribute(k_scatter, cudaFuncAttributeMaxDynamicSharedMemorySize, scat_smem);

    // setup
    k_init<<<48, 256>>>();
    k_detect<<<(NF * NC / 2) / 256, 256>>>((const unsigned*)conn_raw);
    k_conv<<<(NF * NC) / 256, 256>>>((const int*)conn_raw);
    k_dedup<<<NF, NC>>>();
    k_prep_xc<<<(NB * ND) / 256, 256>>>(x_up, b_dec_up);
    k_cvec<<<NF / 8, 256>>>(W_enc_down, b_dec_up, b_dec_down);
    k_transpose<<<dim3(NF / 32, ND / 32), dim3(32, 8)>>>(W_dec_up, (float*)pWduT, ND, NF);
    k_transpose<<<dim3(NF / 32, ND / 32), dim3(32, 8)>>>(W_dec_down, (float*)pWddT, ND, NF);

    // upstream encode + topk
    k_sgemm<true><<<dim3(NF / BN, NB / BM), 256>>>(xc, W_enc_up, b_enc_up, act, NB, NF, ND);
    k_topk<<<NB, 256, topk_smem>>>(act, (int*)pui, (float*)puv);

    // sampled virtual weights + inverted index
    k_vw<<<NF, 256>>>(W_enc_down);
    k_hist<<<(NF * NC) / 256, 256>>>();
    k_scan<<<1, 1024>>>();
    k_fill<<<(NF * NC) / 256, 256>>>();

    // downstream encode + contributions + topk + decode
    k_sgemm<false><<<dim3(NF / BN, NB / BM), 256>>>(initial_acts, W_enc_down, nullptr, act, NB, NF, ND);
    k_scatter<<<NB, 256, scat_smem>>>(ln_scale, b_enc_down);
    k_topk<<<NB, 256, topk_smem>>>(act, (int*)pdi, (float*)pdv);
    k_decode<<<NB, 256>>>(b_dec_down, (float*)d_out);
}

// round 6
// speedup vs baseline: 1.3928x; 1.3928x over previous
#include <cuda_runtime.h>
#include <cuda_bf16.h>
#include <cstdint>

#define NB 4096
#define ND 768
#define NF 12288
#define NC 256
#define NK 64
#define NCAND 128

// HMMA GEMM tiling (plain bf16, single product)
#define KC 32
#define SMPITCH 80
#define HALF_BYTES (128 * SMPITCH)   // 10240
#define STAGE (2 * HALF_BYTES)       // A + B
#define HMMA_SMEM (2 * STAGE)        // 40960

// ---------------- device scratch ----------------
__device__ float g_act[(size_t)NB * NF];
__device__ float g_WduT[(size_t)NF * ND];     // fp32 [F_up, D] for vw gather
__device__ float g_WddT[(size_t)NF * ND];     // fp32 [F_down, D] for decode
__device__ __nv_bfloat16 g_xb[NB * ND];       // bf16(x_up - b_dec_up)
__device__ __nv_bfloat16 g_iab[NB * ND];      // bf16(initial_acts)
__device__ __nv_bfloat16 g_wub[(size_t)NF * ND];
__device__ __nv_bfloat16 g_web[(size_t)NF * ND];
__device__ float g_vw[NF * NC];
__device__ float g_cvu[NF];
__device__ float g_cvd[NF];
__device__ int   g_upi[NB * NK];
__device__ float g_upv[NB * NK];
__device__ int   g_dni[NB * NK];
__device__ float g_dnv[NB * NK];
__device__ int   g_conn[NF * NC];
__device__ int   g_flag;
__device__ int   g_counts[NF];
__device__ int   g_offs[NF + 1];
__device__ int   g_cursor[NF];
__device__ int   g_invr[NF * NC];
__device__ float g_invw[NF * NC];

// ---------------- PTX helpers ----------------
__device__ __forceinline__ uint32_t smem_u32(const void* p) {
    uint32_t a;
    asm("{ .reg .u64 t; cvta.to.shared.u64 t, %1; cvt.u32.u64 %0, t; }" : "=r"(a) : "l"(p));
    return a;
}
__device__ __forceinline__ void cpasync16(uint32_t s, const void* g) {
    asm volatile("cp.async.cg.shared.global [%0], [%1], 16;" :: "r"(s), "l"(g));
}
__device__ __forceinline__ void ldmx4(uint32_t* r, uint32_t addr) {
    asm volatile("ldmatrix.sync.aligned.m8n8.x4.shared.b16 {%0,%1,%2,%3}, [%4];"
                 : "=r"(r[0]), "=r"(r[1]), "=r"(r[2]), "=r"(r[3]) : "r"(addr));
}
__device__ __forceinline__ void mma16816(float* c, const uint32_t* a, uint32_t b0, uint32_t b1) {
    asm volatile(
        "mma.sync.aligned.m16n8k16.row.col.f32.bf16.bf16.f32 "
        "{%0,%1,%2,%3}, {%4,%5,%6,%7}, {%8,%9}, {%0,%1,%2,%3};"
        : "+f"(c[0]), "+f"(c[1]), "+f"(c[2]), "+f"(c[3])
        : "r"(a[0]), "r"(a[1]), "r"(a[2]), "r"(a[3]), "r"(b0), "r"(b1));
}

__device__ __forceinline__ unsigned fkey(float x) {
    unsigned u = __float_as_uint(x);
    return (u & 0x80000000u) ? ~u : (u | 0x80000000u);
}

// Exact sequential ascending-k dot, matching R1's SGEMM accumulation bit-for-bit:
// single fp32 accumulator, FFMA chain over k = 0..ND-1.
__device__ __forceinline__ float seqdot(const float* __restrict__ w, const float* xr) {
    const float4* w4 = (const float4*)w;
    const float4* x4 = (const float4*)xr;
    float acc = 0.f;
#pragma unroll 4
    for (int k = 0; k < ND / 4; k++) {
        float4 wv = w4[k];
        float4 xv = x4[k];
        acc = fmaf(xv.x, wv.x, acc);
        acc = fmaf(xv.y, wv.y, acc);
        acc = fmaf(xv.z, wv.z, acc);
        acc = fmaf(xv.w, wv.w, acc);
    }
    return acc;
}

// ---------------- setup kernels ----------------
__global__ void k_init() {
    int i = blockIdx.x * 256 + threadIdx.x;
    if (i < NF) { g_counts[i] = 0; g_cursor[i] = 0; }
    if (i == 0) g_flag = 0;
}

__global__ void k_detect(const unsigned* __restrict__ raw) {
    int i = blockIdx.x * 256 + threadIdx.x;
    bool nz = (raw[2 * i + 1] != 0u);
    if (__syncthreads_or(nz) && threadIdx.x == 0) atomicOr(&g_flag, 1);
}

__global__ void k_conv(const int* __restrict__ raw) {
    int i = blockIdx.x * 256 + threadIdx.x;
    g_conn[i] = g_flag ? raw[i] : raw[2 * i];
}

__global__ void k_dedup() {
    __shared__ unsigned bm[NF / 32];
    int r = blockIdx.x;
    for (int i = threadIdx.x; i < NF / 32; i += NC) bm[i] = 0;
    __syncthreads();
    int c = threadIdx.x;
    int j = g_conn[r * NC + c];
    unsigned bit = 1u << (j & 31);
    unsigned old = atomicOr(&bm[j >> 5], bit);
    if (old & bit) g_conn[r * NC + c] = -1;
}

// fp32 -> bf16 convert, optional per-column bias subtract (period ND)
__global__ void k_tobf(const float* __restrict__ in, const float* __restrict__ sub,
                       __nv_bfloat16* __restrict__ out) {
    int i = blockIdx.x * 256 + threadIdx.x;
    float x = in[i];
    if (sub) x -= sub[i % ND];
    out[i] = __float2bfloat16(x);
}

__global__ void k_cvec(const float* __restrict__ Wed, const float* __restrict__ bdu,
                       const float* __restrict__ bdd) {
    int r = blockIdx.x * 8 + (threadIdx.x >> 5);
    int lane = threadIdx.x & 31;
    const float* wr = Wed + (size_t)r * ND;
    float s1 = 0.f, s2 = 0.f;
    for (int d = lane; d < ND; d += 32) { float w = wr[d]; s1 += w * bdu[d]; s2 += w * bdd[d]; }
    for (int o = 16; o; o >>= 1) { s1 += __shfl_xor_sync(~0u, s1, o); s2 += __shfl_xor_sync(~0u, s2, o); }
    if (!lane) { g_cvu[r] = s1; g_cvd[r] = s2; }
}

__global__ void k_transpose(const float* __restrict__ in, float* __restrict__ out,
                            int rows, int cols) {
    __shared__ float tile[32][33];
    int c0 = blockIdx.x * 32, r0 = blockIdx.y * 32;
    int x = threadIdx.x, y = threadIdx.y;
    for (int i = 0; i < 32; i += 8)
        tile[y + i][x] = in[(size_t)(r0 + y + i) * cols + c0 + x];
    __syncthreads();
    for (int i = 0; i < 32; i += 8)
        out[(size_t)(c0 + y + i) * rows + r0 + x] = tile[x][y + i];
}

// ---------------- plain-bf16 HMMA GEMM: C[M,N] = A[M,K] * B[N,K]^T ----------------
template <bool RELU, bool BIAS>
__global__ __launch_bounds__(256)
void k_hmma(const __nv_bfloat16* __restrict__ A, const __nv_bfloat16* __restrict__ B,
            const float* __restrict__ bias, float* __restrict__ C, int N) {
    extern __shared__ unsigned char sm[];
    uint32_t sb = smem_u32(sm);
    int tid = threadIdx.x, wid = tid >> 5, lane = tid & 31;
    int bm = blockIdx.y * 128, bn = blockIdx.x * 128;
    int wm = (wid >> 2) * 64, wn = (wid & 3) * 32;

    const char* gA = (const char*)(A + (size_t)bm * ND);
    const char* gB = (const char*)(B + (size_t)bn * ND);

    float acc[4][4][4];
#pragma unroll
    for (int mi = 0; mi < 4; mi++)
#pragma unroll
        for (int ni = 0; ni < 4; ni++)
#pragma unroll
            for (int q = 0; q < 4; q++) acc[mi][ni][q] = 0.f;

    int l_row = tid >> 1;
    int l_q2 = (tid & 1) * 2;
    auto load_stage = [&](int buf, int kc) {
        uint32_t s0 = sb + buf * STAGE;
        const char* srcs[2] = { gA + kc * (KC * 2), gB + kc * (KC * 2) };
#pragma unroll
        for (int h = 0; h < 2; h++) {
            uint32_t so = s0 + h * HALF_BYTES + l_row * SMPITCH + l_q2 * 16;
            const char* gp = srcs[h] + (size_t)l_row * (ND * 2) + l_q2 * 16;
            cpasync16(so, gp);
            cpasync16(so + 16, gp + 16);
        }
        asm volatile("cp.async.commit_group;" ::: "memory");
    };

    load_stage(0, 0);

    const int NCH = ND / KC;  // 24
    for (int i = 0; i < NCH; i++) {
        if (i + 1 < NCH) {
            load_stage((i + 1) & 1, i + 1);
            asm volatile("cp.async.wait_group 1;" ::: "memory");
        } else {
            asm volatile("cp.async.wait_group 0;" ::: "memory");
        }
        __syncthreads();

        uint32_t s0 = sb + (i & 1) * STAGE;
        uint32_t aB = s0, bB = s0 + HALF_BYTES;
        int lrow = lane & 15;
        int lcol = (lane >> 4) * 8;
#pragma unroll
        for (int ks = 0; ks < 2; ks++) {
            uint32_t aoff = (uint32_t)((wm + lrow) * SMPITCH + (lcol + ks * 16) * 2);
            uint32_t boff = (uint32_t)((wn + lrow) * SMPITCH + (lcol + ks * 16) * 2);
            uint32_t a[4][4], b[2][4];
#pragma unroll
            for (int mi = 0; mi < 4; mi++) ldmx4(a[mi], aB + aoff + mi * 16 * SMPITCH);
#pragma unroll
            for (int nj = 0; nj < 2; nj++) ldmx4(b[nj], bB + boff + nj * 16 * SMPITCH);
#pragma unroll
            for (int mi = 0; mi < 4; mi++)
#pragma unroll
                for (int ni = 0; ni < 4; ni++) {
                    int nj = ni >> 1, o = ni & 1;
                    mma16816(acc[mi][ni], a[mi], b[nj][o], b[nj][o + 2]);
                }
        }
        __syncthreads();
    }

    int gid = lane >> 2, qc = (lane & 3) * 2;
#pragma unroll
    for (int mi = 0; mi < 4; mi++)
#pragma unroll
        for (int ni = 0; ni < 4; ni++) {
            int col = bn + wn + ni * 8 + qc;
            float bx = 0.f, by = 0.f;
            if (BIAS) { float2 b2 = *(const float2*)&bias[col]; bx = b2.x; by = b2.y; }
#pragma unroll
            for (int h = 0; h < 2; h++) {
                int row = bm + wm + mi * 16 + gid + h * 8;
                float x = acc[mi][ni][2 * h] + bx;
                float y = acc[mi][ni][2 * h + 1] + by;
                if (RELU) { x = fmaxf(x, 0.f); y = fmaxf(y, 0.f); }
                *(float2*)&C[(size_t)row * N + col] = make_float2(x, y);
            }
        }
}

// ---------------- shared screen helper: radix-select top-NCAND candidates ----------------
struct ScreenSh { int bin, above, ca, ce; };

__device__ __forceinline__ void screen_collect(const float* vals, int* hist, int* cand,
                                               ScreenSh* sh) {
    unsigned prefix = 0;
    int need = NCAND, tot = 0;
    for (int lev = 0; lev < 4; lev++) {
        int shift = 24 - 8 * lev;
        if (threadIdx.x < 256) hist[threadIdx.x] = 0;
        __syncthreads();
        for (int i = threadIdx.x; i < NF; i += 256) {
            unsigned k = fkey(vals[i]);
            if (lev == 0 || (k >> (shift + 8)) == prefix)
                atomicAdd(&hist[(k >> shift) & 255], 1);
        }
        __syncthreads();
        if (threadIdx.x == 0) {
            int acc = 0, bb = 255;
            for (;;) { acc += hist[bb]; if (acc >= need || bb == 0) break; bb--; }
            sh->bin = bb;
            sh->above = acc - hist[bb];
        }
        __syncthreads();
        prefix = (prefix << 8) | (unsigned)sh->bin;
        need -= sh->above;
        tot += sh->above;
        __syncthreads();
    }
    if (threadIdx.x == 0) { sh->ca = 0; sh->ce = 0; }
    __syncthreads();
    for (int i = threadIdx.x; i < NF; i += 256) {
        unsigned k = fkey(vals[i]);
        if (k > prefix) {
            int p = atomicAdd(&sh->ca, 1);
            cand[p] = i;
        } else if (k == prefix) {
            int p = atomicAdd(&sh->ce, 1);
            if (p < need) cand[tot + p] = i;
        }
    }
    __syncthreads();
}

// ---------------- upstream: screen + exact sequential-fp32 rescore + top-64 ----------------
__global__ __launch_bounds__(256)
void k_topk_up(const float* __restrict__ act, const float* __restrict__ x_up,
               const float* __restrict__ bdu, const float* __restrict__ Wenc,
               const float* __restrict__ benc,
               int* __restrict__ oidx, float* __restrict__ oval) {
    extern __shared__ unsigned char smraw[];
    float* vals = (float*)smraw;                       // NF
    int* hist = (int*)(vals + NF);                     // 256
    float* xr = (float*)(hist + 256);                  // ND (16B aligned)
    int* cand = (int*)(xr + ND);                       // NCAND
    float* cex = (float*)(cand + NCAND);               // NCAND
    __shared__ ScreenSh sh;
    int b = blockIdx.x;
    const float* row = act + (size_t)b * NF;
    for (int i = threadIdx.x; i < NF; i += 256) vals[i] = row[i];
    for (int d = threadIdx.x; d < ND; d += 256) xr[d] = x_up[(size_t)b * ND + d] - bdu[d];
    __syncthreads();

    screen_collect(vals, hist, cand, &sh);

    // exact rescore: one thread per candidate, R1-identical arithmetic
    if (threadIdx.x < NCAND) {
        int j = cand[threadIdx.x];
        float s = seqdot(Wenc + (size_t)j * ND, xr);
        cex[threadIdx.x] = fmaxf(s + benc[j], 0.f);
    }
    __syncthreads();

    if (threadIdx.x < NCAND) {
        float v = cex[threadIdx.x];
        int rank = 0;
        for (int u = 0; u < NCAND; u++) {
            float w = cex[u];
            rank += (w > v) || (w == v && u < (int)threadIdx.x);
        }
        if (rank < NK) { oidx[b * NK + rank] = cand[threadIdx.x]; oval[b * NK + rank] = v; }
    }
}

// ---------------- sampled virtual weights (fp32) ----------------
__global__ __launch_bounds__(256)
void k_vw(const float* __restrict__ Wed) {
    __shared__ float arow[ND];
    int r = blockIdx.x;
    for (int d = threadIdx.x; d < ND; d += 256) arow[d] = Wed[(size_t)r * ND + d];
    __syncthreads();
    int warp = threadIdx.x >> 5, lane = threadIdx.x & 31;
    for (int c = warp; c < NC; c += 8) {
        int j = g_conn[r * NC + c];
        float s = 0.f;
        if (j >= 0) {
            const float* wr = g_WduT + (size_t)j * ND;
            for (int d = lane; d < ND; d += 32) s += arow[d] * wr[d];
        }
        for (int o = 16; o; o >>= 1) s += __shfl_xor_sync(~0u, s, o);
        if (!lane) g_vw[r * NC + c] = s;
    }
}

// ---------------- inverted connection index ----------------
__global__ void k_hist() {
    int i = blockIdx.x * 256 + threadIdx.x;
    int j = g_conn[i];
    if (j >= 0) atomicAdd(&g_counts[j], 1);
}

__global__ void k_scan() {
    __shared__ int part[1024];
    int t = threadIdx.x;
    int base = t * 12;
    int loc[12], s = 0;
    for (int i = 0; i < 12; i++) { loc[i] = s; s += g_counts[base + i]; }
    part[t] = s;
    __syncthreads();
    for (int o = 1; o < 1024; o <<= 1) {
        int v = (t >= o) ? part[t - o] : 0;
        __syncthreads();
        part[t] += v;
        __syncthreads();
    }
    int excl = part[t] - s;
    for (int i = 0; i < 12; i++) g_offs[base + i] = excl + loc[i];
    if (t == 1023) g_offs[NF] = part[1023];
}

__global__ void k_fill() {
    int i = blockIdx.x * 256 + threadIdx.x;
    int j = g_conn[i];
    if (j >= 0) {
        int p = atomicAdd(&g_cursor[j], 1);
        int e = g_offs[j] + p;
        g_invr[e] = i >> 8;
        g_invw[e] = g_vw[i];
    }
}

// ---------------- down: scatter + screen + exact sequential rescore + top-64 ----------------
__global__ __launch_bounds__(256)
void k_down(const float* __restrict__ act, const float* __restrict__ ia,
            const float* __restrict__ Wed, const float* __restrict__ lnscale,
            const float* __restrict__ bencd,
            int* __restrict__ oidx, float* __restrict__ oval) {
    extern __shared__ unsigned char smraw[];
    float* contrib = (float*)smraw;                    // NF
    float* vals = contrib + NF;                        // NF
    int* hist = (int*)(vals + NF);                     // 256
    float* iar = (float*)(hist + 256);                 // ND (16B aligned)
    int* cand = (int*)(iar + ND);                      // NCAND
    float* cex = (float*)(cand + NCAND);               // NCAND
    __shared__ ScreenSh sh;
    int b = blockIdx.x;
    for (int i = threadIdx.x; i < NF; i += 256) contrib[i] = 0.f;
    for (int d = threadIdx.x; d < ND; d += 256) iar[d] = ia[(size_t)b * ND + d];
    __syncthreads();

    int wid = threadIdx.x >> 5, lane = threadIdx.x & 31;
    for (int t = wid; t < NK; t += 8) {
        float v = g_upv[b * NK + t];
        int j = g_upi[b * NK + t];
        if (v != 0.f) {
            int e0 = g_offs[j], e1 = g_offs[j + 1];
            for (int e = e0 + lane; e < e1; e += 32)
                atomicAdd(&contrib[g_invr[e]], v * g_invw[e]);
        }
    }
    __syncthreads();
    float ls = lnscale[b];
    const float* arow = act + (size_t)b * NF;
    for (int i = threadIdx.x; i < NF; i += 256)
        vals[i] = __fdiv_rn(arow[i] + contrib[i] + g_cvu[i], ls) + bencd[i] - g_cvd[i];
    __syncthreads();

    screen_collect(vals, hist, cand, &sh);

    // exact rescore: one thread per candidate, R1-identical arithmetic
    if (threadIdx.x < NCAND) {
        int r = cand[threadIdx.x];
        float s = seqdot(Wed + (size_t)r * ND, iar);
        cex[threadIdx.x] = __fdiv_rn(s + contrib[r] + g_cvu[r], ls) + bencd[r] - g_cvd[r];
    }
    __syncthreads();

    if (threadIdx.x < NCAND) {
        float v = cex[threadIdx.x];
        int rank = 0;
        for (int u = 0; u < NCAND; u++) {
            float w = cex[u];
            rank += (w > v) || (w == v && u < (int)threadIdx.x);
        }
        if (rank < NK) { oidx[b * NK + rank] = cand[threadIdx.x]; oval[b * NK + rank] = v; }
    }
}

// ---------------- sparse decode (fp32) ----------------
__global__ __launch_bounds__(256)
void k_decode(const float* __restrict__ bdd, float* __restrict__ out) {
    __shared__ int sj[NK];
    __shared__ float sv[NK];
    int b = blockIdx.x;
    if (threadIdx.x < NK) {
        sj[threadIdx.x] = g_dni[b * NK + threadIdx.x];
        sv[threadIdx.x] = g_dnv[b * NK + threadIdx.x];
    }
    __syncthreads();
    for (int d = threadIdx.x; d < ND; d += 256) {
        float acc = bdd[d];
        for (int t = 0; t < NK; t++)
            acc += sv[t] * g_WddT[(size_t)sj[t] * ND + d];
        out[(size_t)b * ND + d] = acc;
    }
}

// ---------------- launch ----------------
extern "C" void kernel_launch(void* const* d_in, const int* in_sizes, int n_in,
                              void* d_out, int out_size) {
    const float* initial_acts = (const float*)d_in[0];
    const float* x_up        = (const float*)d_in[1];
    const float* ln_scale    = (const float*)d_in[2];
    const float* W_enc_up    = (const float*)d_in[3];
    const float* b_enc_up    = (const float*)d_in[4];
    const float* b_dec_up    = (const float*)d_in[5];
    const float* W_dec_up    = (const float*)d_in[6];
    const float* W_enc_down  = (const float*)d_in[7];
    const float* b_enc_down  = (const float*)d_in[8];
    const float* b_dec_down  = (const float*)d_in[9];
    const float* W_dec_down  = (const float*)d_in[10];
    const void*  conn_raw    = d_in[11];

    void *pa, *pWduT, *pWddT, *pui, *puv, *pdi, *pdv, *pxb, *piab, *pwub, *pweb;
    cudaGetSymbolAddress(&pa, g_act);
    cudaGetSymbolAddress(&pWduT, g_WduT);
    cudaGetSymbolAddress(&pWddT, g_WddT);
    cudaGetSymbolAddress(&pui, g_upi);
    cudaGetSymbolAddress(&puv, g_upv);
    cudaGetSymbolAddress(&pdi, g_dni);
    cudaGetSymbolAddress(&pdv, g_dnv);
    cudaGetSymbolAddress(&pxb, g_xb);
    cudaGetSymbolAddress(&piab, g_iab);
    cudaGetSymbolAddress(&pwub, g_wub);
    cudaGetSymbolAddress(&pweb, g_web);
    float* act = (float*)pa;

    const int up_smem = (NF + 256 + ND + 2 * NCAND) * 4;            // 54528
    const int dn_smem = (2 * NF + 256 + ND + 2 * NCAND) * 4;        // 103680
    cudaFuncSetAttribute(k_topk_up, cudaFuncAttributeMaxDynamicSharedMemorySize, up_smem);
    cudaFuncSetAttribute(k_down, cudaFuncAttributeMaxDynamicSharedMemorySize, dn_smem);
    cudaFuncSetAttribute(k_hmma<true, true>, cudaFuncAttributeMaxDynamicSharedMemorySize, HMMA_SMEM);
    cudaFuncSetAttribute(k_hmma<false, false>, cudaFuncAttributeMaxDynamicSharedMemorySize, HMMA_SMEM);

    // setup
    k_init<<<48, 256>>>();
    k_detect<<<(NF * NC / 2) / 256, 256>>>((const unsigned*)conn_raw);
    k_conv<<<(NF * NC) / 256, 256>>>((const int*)conn_raw);
    k_dedup<<<NF, NC>>>();
    k_cvec<<<NF / 8, 256>>>(W_enc_down, b_dec_up, b_dec_down);

    // bf16 operands for screening GEMMs
    k_tobf<<<(NB * ND) / 256, 256>>>(x_up, b_dec_up, (__nv_bfloat16*)pxb);
    k_tobf<<<(NB * ND) / 256, 256>>>(initial_acts, nullptr, (__nv_bfloat16*)piab);
    k_tobf<<<(NF * ND) / 256, 256>>>(W_enc_up, nullptr, (__nv_bfloat16*)pwub);
    k_tobf<<<(NF * ND) / 256, 256>>>(W_enc_down, nullptr, (__nv_bfloat16*)pweb);

    // fp32 transposes
    k_transpose<<<dim3(NF / 32, ND / 32), dim3(32, 8)>>>(W_dec_up, (float*)pWduT, ND, NF);
    k_transpose<<<dim3(NF / 32, ND / 32), dim3(32, 8)>>>(W_dec_down, (float*)pWddT, ND, NF);

    // upstream: approx GEMM -> screen + exact rescore
    k_hmma<true, true><<<dim3(NF / 128, NB / 128), 256, HMMA_SMEM>>>(
        (const __nv_bfloat16*)pxb, (const __nv_bfloat16*)pwub, b_enc_up, act, NF);
    k_topk_up<<<NB, 256, up_smem>>>(act, x_up, b_dec_up, W_enc_up, b_enc_up,
                                    (int*)pui, (float*)puv);

    // sampled virtual weights + inverted index
    k_vw<<<NF, 256>>>(W_enc_down);
    k_hist<<<(NF * NC) / 256, 256>>>();
    k_scan<<<1, 1024>>>();
    k_fill<<<(NF * NC) / 256, 256>>>();

    // downstream: approx GEMM -> scatter + screen + exact rescore -> decode
    k_hmma<false, false><<<dim3(NF / 128, NB / 128), 256, HMMA_SMEM>>>(
        (const __nv_bfloat16*)piab, (const __nv_bfloat16*)pweb, nullptr, act, NF);
    k_down<<<NB, 256, dn_smem>>>(act, initial_acts, W_enc_down, ln_scale, b_enc_down,
                                 (int*)pdi, (float*)pdv);
    k_decode<<<NB, 256>>>(b_dec_down, (float*)d_out);
}

// round 7
// speedup vs baseline: 1.4714x; 1.0564x over previous
#include <cuda_runtime.h>
#include <cuda_bf16.h>
#include <cstdint>

#define NB 4096
#define ND 768
#define NF 12288
#define NC 256
#define NK 64
#define NCAND 128

// HMMA GEMM tiling (plain bf16, single product)
#define KC 32
#define SMPITCH 80
#define HALF_BYTES (128 * SMPITCH)   // 10240
#define STAGE (2 * HALF_BYTES)       // A + B
#define HMMA_SMEM (2 * STAGE)        // 40960

// ---------------- device scratch ----------------
__device__ float g_act[(size_t)NB * NF];
__device__ float g_act2[(size_t)NB * NF];
__device__ float g_WduT[(size_t)NF * ND];     // fp32 [F_up, D] for vw gather
__device__ float g_WddT[(size_t)NF * ND];     // fp32 [F_down, D] for decode
__device__ __nv_bfloat16 g_xb[NB * ND];
__device__ __nv_bfloat16 g_iab[NB * ND];
__device__ __nv_bfloat16 g_wub[(size_t)NF * ND];
__device__ __nv_bfloat16 g_web[(size_t)NF * ND];
__device__ float g_vw[NF * NC];
__device__ float g_cvu[NF];
__device__ float g_cvd[NF];
__device__ int   g_upi[NB * NK];
__device__ float g_upv[NB * NK];
__device__ int   g_dni[NB * NK];
__device__ float g_dnv[NB * NK];
__device__ int   g_conn[NF * NC];
__device__ int   g_flag;
__device__ int   g_counts[NF];
__device__ int   g_offs[NF + 1];
__device__ int   g_cursor[NF];
__device__ int   g_invr[NF * NC];
__device__ float g_invw[NF * NC];

// ---------------- PTX helpers ----------------
__device__ __forceinline__ uint32_t smem_u32(const void* p) {
    uint32_t a;
    asm("{ .reg .u64 t; cvta.to.shared.u64 t, %1; cvt.u32.u64 %0, t; }" : "=r"(a) : "l"(p));
    return a;
}
__device__ __forceinline__ void cpasync16(uint32_t s, const void* g) {
    asm volatile("cp.async.cg.shared.global [%0], [%1], 16;" :: "r"(s), "l"(g));
}
__device__ __forceinline__ void ldmx4(uint32_t* r, uint32_t addr) {
    asm volatile("ldmatrix.sync.aligned.m8n8.x4.shared.b16 {%0,%1,%2,%3}, [%4];"
                 : "=r"(r[0]), "=r"(r[1]), "=r"(r[2]), "=r"(r[3]) : "r"(addr));
}
__device__ __forceinline__ void mma16816(float* c, const uint32_t* a, uint32_t b0, uint32_t b1) {
    asm volatile(
        "mma.sync.aligned.m16n8k16.row.col.f32.bf16.bf16.f32 "
        "{%0,%1,%2,%3}, {%4,%5,%6,%7}, {%8,%9}, {%0,%1,%2,%3};"
        : "+f"(c[0]), "+f"(c[1]), "+f"(c[2]), "+f"(c[3])
        : "r"(a[0]), "r"(a[1]), "r"(a[2]), "r"(a[3]), "r"(b0), "r"(b1));
}

__device__ __forceinline__ unsigned fkey(float x) {
    unsigned u = __float_as_uint(x);
    return (u & 0x80000000u) ? ~u : (u | 0x80000000u);
}

// Exact sequential ascending-k dot (R1-identical arithmetic for rescore)
__device__ __forceinline__ float seqdot(const float* __restrict__ w, const float* xr) {
    const float4* w4 = (const float4*)w;
    const float4* x4 = (const float4*)xr;
    float acc = 0.f;
#pragma unroll 4
    for (int k = 0; k < ND / 4; k++) {
        float4 wv = w4[k];
        float4 xv = x4[k];
        acc = fmaf(xv.x, wv.x, acc);
        acc = fmaf(xv.y, wv.y, acc);
        acc = fmaf(xv.z, wv.z, acc);
        acc = fmaf(xv.w, wv.w, acc);
    }
    return acc;
}

// ---------------- setup kernels ----------------
__global__ void k_init() {
    int i = blockIdx.x * 256 + threadIdx.x;
    if (i < NF) { g_counts[i] = 0; g_cursor[i] = 0; }
    if (i == 0) g_flag = 0;
}

__global__ void k_detect(const unsigned* __restrict__ raw) {
    int i = blockIdx.x * 256 + threadIdx.x;
    bool nz = (raw[2 * i + 1] != 0u);
    if (__syncthreads_or(nz) && threadIdx.x == 0) atomicOr(&g_flag, 1);
}

__global__ void k_conv(const int* __restrict__ raw) {
    int i = blockIdx.x * 256 + threadIdx.x;
    g_conn[i] = g_flag ? raw[i] : raw[2 * i];
}

__global__ void k_dedup() {
    __shared__ unsigned bm[NF / 32];
    int r = blockIdx.x;
    for (int i = threadIdx.x; i < NF / 32; i += NC) bm[i] = 0;
    __syncthreads();
    int c = threadIdx.x;
    int j = g_conn[r * NC + c];
    unsigned bit = 1u << (j & 31);
    unsigned old = atomicOr(&bm[j >> 5], bit);
    if (old & bit) g_conn[r * NC + c] = -1;
}

__global__ void k_tobf(const float* __restrict__ in, const float* __restrict__ sub,
                       __nv_bfloat16* __restrict__ out) {
    int i = blockIdx.x * 256 + threadIdx.x;
    float x = in[i];
    if (sub) x -= sub[i % ND];
    out[i] = __float2bfloat16(x);
}

__global__ void k_cvec(const float* __restrict__ Wed, const float* __restrict__ bdu,
                       const float* __restrict__ bdd) {
    int r = blockIdx.x * 8 + (threadIdx.x >> 5);
    int lane = threadIdx.x & 31;
    const float* wr = Wed + (size_t)r * ND;
    float s1 = 0.f, s2 = 0.f;
    for (int d = lane; d < ND; d += 32) { float w = wr[d]; s1 += w * bdu[d]; s2 += w * bdd[d]; }
    for (int o = 16; o; o >>= 1) { s1 += __shfl_xor_sync(~0u, s1, o); s2 += __shfl_xor_sync(~0u, s2, o); }
    if (!lane) { g_cvu[r] = s1; g_cvd[r] = s2; }
}

__global__ void k_transpose(const float* __restrict__ in, float* __restrict__ out,
                            int rows, int cols) {
    __shared__ float tile[32][33];
    int c0 = blockIdx.x * 32, r0 = blockIdx.y * 32;
    int x = threadIdx.x, y = threadIdx.y;
    for (int i = 0; i < 32; i += 8)
        tile[y + i][x] = in[(size_t)(r0 + y + i) * cols + c0 + x];
    __syncthreads();
    for (int i = 0; i < 32; i += 8)
        out[(size_t)(c0 + y + i) * rows + r0 + x] = tile[x][y + i];
}

// ---------------- plain-bf16 HMMA GEMM: C[M,N] = A[M,K] * B[N,K]^T ----------------
template <bool RELU, bool BIAS>
__global__ __launch_bounds__(256)
void k_hmma(const __nv_bfloat16* __restrict__ A, const __nv_bfloat16* __restrict__ B,
            const float* __restrict__ bias, float* __restrict__ C, int N) {
    extern __shared__ unsigned char sm[];
    uint32_t sb = smem_u32(sm);
    int tid = threadIdx.x, wid = tid >> 5, lane = tid & 31;
    int bm = blockIdx.y * 128, bn = blockIdx.x * 128;
    int wm = (wid >> 2) * 64, wn = (wid & 3) * 32;

    const char* gA = (const char*)(A + (size_t)bm * ND);
    const char* gB = (const char*)(B + (size_t)bn * ND);

    float acc[4][4][4];
#pragma unroll
    for (int mi = 0; mi < 4; mi++)
#pragma unroll
        for (int ni = 0; ni < 4; ni++)
#pragma unroll
            for (int q = 0; q < 4; q++) acc[mi][ni][q] = 0.f;

    int l_row = tid >> 1;
    int l_q2 = (tid & 1) * 2;
    auto load_stage = [&](int buf, int kc) {
        uint32_t s0 = sb + buf * STAGE;
        const char* srcs[2] = { gA + kc * (KC * 2), gB + kc * (KC * 2) };
#pragma unroll
        for (int h = 0; h < 2; h++) {
            uint32_t so = s0 + h * HALF_BYTES + l_row * SMPITCH + l_q2 * 16;
            const char* gp = srcs[h] + (size_t)l_row * (ND * 2) + l_q2 * 16;
            cpasync16(so, gp);
            cpasync16(so + 16, gp + 16);
        }
        asm volatile("cp.async.commit_group;" ::: "memory");
    };

    load_stage(0, 0);

    const int NCH = ND / KC;  // 24
    for (int i = 0; i < NCH; i++) {
        if (i + 1 < NCH) {
            load_stage((i + 1) & 1, i + 1);
            asm volatile("cp.async.wait_group 1;" ::: "memory");
        } else {
            asm volatile("cp.async.wait_group 0;" ::: "memory");
        }
        __syncthreads();

        uint32_t s0 = sb + (i & 1) * STAGE;
        uint32_t aB = s0, bB = s0 + HALF_BYTES;
        int lrow = lane & 15;
        int lcol = (lane >> 4) * 8;
#pragma unroll
        for (int ks = 0; ks < 2; ks++) {
            uint32_t aoff = (uint32_t)((wm + lrow) * SMPITCH + (lcol + ks * 16) * 2);
            uint32_t boff = (uint32_t)((wn + lrow) * SMPITCH + (lcol + ks * 16) * 2);
            uint32_t a[4][4], b[2][4];
#pragma unroll
            for (int mi = 0; mi < 4; mi++) ldmx4(a[mi], aB + aoff + mi * 16 * SMPITCH);
#pragma unroll
            for (int nj = 0; nj < 2; nj++) ldmx4(b[nj], bB + boff + nj * 16 * SMPITCH);
#pragma unroll
            for (int mi = 0; mi < 4; mi++)
#pragma unroll
                for (int ni = 0; ni < 4; ni++) {
                    int nj = ni >> 1, o = ni & 1;
                    mma16816(acc[mi][ni], a[mi], b[nj][o], b[nj][o + 2]);
                }
        }
        __syncthreads();
    }

    int gid = lane >> 2, qc = (lane & 3) * 2;
#pragma unroll
    for (int mi = 0; mi < 4; mi++)
#pragma unroll
        for (int ni = 0; ni < 4; ni++) {
            int col = bn + wn + ni * 8 + qc;
            float bx = 0.f, by = 0.f;
            if (BIAS) { float2 b2 = *(const float2*)&bias[col]; bx = b2.x; by = b2.y; }
#pragma unroll
            for (int h = 0; h < 2; h++) {
                int row = bm + wm + mi * 16 + gid + h * 8;
                float x = acc[mi][ni][2 * h] + bx;
                float y = acc[mi][ni][2 * h + 1] + by;
                if (RELU) { x = fmaxf(x, 0.f); y = fmaxf(y, 0.f); }
                *(float2*)&C[(size_t)row * N + col] = make_float2(x, y);
            }
        }
}

// ---------------- shared screen helper: radix-select top-NCAND candidates ----------------
struct ScreenSh { int bin, above, ca, ce; };

__device__ __forceinline__ void screen_collect(const float* vals, int* hist, int* cand,
                                               ScreenSh* sh) {
    unsigned prefix = 0;
    int need = NCAND, tot = 0;
    for (int lev = 0; lev < 4; lev++) {
        int shift = 24 - 8 * lev;
        if (threadIdx.x < 256) hist[threadIdx.x] = 0;
        __syncthreads();
        for (int i = threadIdx.x; i < NF; i += 256) {
            unsigned k = fkey(vals[i]);
            if (lev == 0 || (k >> (shift + 8)) == prefix)
                atomicAdd(&hist[(k >> shift) & 255], 1);
        }
        __syncthreads();
        if (threadIdx.x == 0) {
            int acc = 0, bb = 255;
            for (;;) { acc += hist[bb]; if (acc >= need || bb == 0) break; bb--; }
            sh->bin = bb;
            sh->above = acc - hist[bb];
        }
        __syncthreads();
        prefix = (prefix << 8) | (unsigned)sh->bin;
        need -= sh->above;
        tot += sh->above;
        __syncthreads();
    }
    if (threadIdx.x == 0) { sh->ca = 0; sh->ce = 0; }
    __syncthreads();
    for (int i = threadIdx.x; i < NF; i += 256) {
        unsigned k = fkey(vals[i]);
        if (k > prefix) {
            int p = atomicAdd(&sh->ca, 1);
            cand[p] = i;
        } else if (k == prefix) {
            int p = atomicAdd(&sh->ce, 1);
            if (p < need) cand[tot + p] = i;
        }
    }
    __syncthreads();
}

// ---------------- upstream: screen + exact sequential rescore + top-64 ----------------
__global__ __launch_bounds__(256)
void k_topk_up(const float* __restrict__ act, const float* __restrict__ x_up,
               const float* __restrict__ bdu, const float* __restrict__ Wenc,
               const float* __restrict__ benc,
               int* __restrict__ oidx, float* __restrict__ oval) {
    extern __shared__ unsigned char smraw[];
    float* vals = (float*)smraw;                       // NF
    int* hist = (int*)(vals + NF);                     // 256
    float* xr = (float*)(hist + 256);                  // ND
    int* cand = (int*)(xr + ND);                       // NCAND
    float* cex = (float*)(cand + NCAND);               // NCAND
    __shared__ ScreenSh sh;
    int b = blockIdx.x;
    const float4* row4 = (const float4*)(act + (size_t)b * NF);
    float4* vals4 = (float4*)vals;
    for (int i = threadIdx.x; i < NF / 4; i += 256) vals4[i] = row4[i];
    for (int d = threadIdx.x; d < ND; d += 256) xr[d] = x_up[(size_t)b * ND + d] - bdu[d];
    __syncthreads();

    screen_collect(vals, hist, cand, &sh);

    if (threadIdx.x < NCAND) {
        int j = cand[threadIdx.x];
        float s = seqdot(Wenc + (size_t)j * ND, xr);
        cex[threadIdx.x] = fmaxf(s + benc[j], 0.f);
    }
    __syncthreads();

    if (threadIdx.x < NCAND) {
        float v = cex[threadIdx.x];
        int rank = 0;
        for (int u = 0; u < NCAND; u++) {
            float w = cex[u];
            rank += (w > v) || (w == v && u < (int)threadIdx.x);
        }
        if (rank < NK) { oidx[b * NK + rank] = cand[threadIdx.x]; oval[b * NK + rank] = v; }
    }
}

// ---------------- sampled virtual weights (fp32, float4 gather) ----------------
__global__ __launch_bounds__(256)
void k_vw(const float* __restrict__ Wed) {
    __shared__ float4 arow[ND / 4];
    int r = blockIdx.x;
    const float4* wr4 = (const float4*)(Wed + (size_t)r * ND);
    for (int d = threadIdx.x; d < ND / 4; d += 256) arow[d] = wr4[d];
    __syncthreads();
    int warp = threadIdx.x >> 5, lane = threadIdx.x & 31;
    for (int c = warp; c < NC; c += 8) {
        int j = g_conn[r * NC + c];
        float s = 0.f;
        if (j >= 0) {
            const float4* w4 = (const float4*)(g_WduT + (size_t)j * ND);
#pragma unroll
            for (int d = lane; d < ND / 4; d += 32) {
                float4 w = w4[d];
                float4 a = arow[d];
                s += a.x * w.x + a.y * w.y + a.z * w.z + a.w * w.w;
            }
        }
        for (int o = 16; o; o >>= 1) s += __shfl_xor_sync(~0u, s, o);
        if (!lane) g_vw[r * NC + c] = s;
    }
}

// ---------------- inverted connection index ----------------
__global__ void k_hist() {
    int i = blockIdx.x * 256 + threadIdx.x;
    int j = g_conn[i];
    if (j >= 0) atomicAdd(&g_counts[j], 1);
}

__global__ void k_scan() {
    __shared__ int part[1024];
    int t = threadIdx.x;
    int base = t * 12;
    int loc[12], s = 0;
    for (int i = 0; i < 12; i++) { loc[i] = s; s += g_counts[base + i]; }
    part[t] = s;
    __syncthreads();
    for (int o = 1; o < 1024; o <<= 1) {
        int v = (t >= o) ? part[t - o] : 0;
        __syncthreads();
        part[t] += v;
        __syncthreads();
    }
    int excl = part[t] - s;
    for (int i = 0; i < 12; i++) g_offs[base + i] = excl + loc[i];
    if (t == 1023) g_offs[NF] = part[1023];
}

__global__ void k_fill() {
    int i = blockIdx.x * 256 + threadIdx.x;
    int j = g_conn[i];
    if (j >= 0) {
        int p = atomicAdd(&g_cursor[j], 1);
        int e = g_offs[j] + p;
        g_invr[e] = i >> 8;
        g_invw[e] = g_vw[i];
    }
}

// ---------------- down: scatter + screen + exact rescore + top-64 ----------------
__global__ __launch_bounds__(256)
void k_down(const float* __restrict__ act, const float* __restrict__ ia,
            const float* __restrict__ Wed, const float* __restrict__ lnscale,
            const float* __restrict__ bencd,
            int* __restrict__ oidx, float* __restrict__ oval) {
    extern __shared__ unsigned char smraw[];
    float* contrib = (float*)smraw;                    // NF
    float* vals = contrib + NF;                        // NF
    int* hist = (int*)(vals + NF);                     // 256
    float* iar = (float*)(hist + 256);                 // ND
    int* cand = (int*)(iar + ND);                      // NCAND
    float* cex = (float*)(cand + NCAND);               // NCAND
    __shared__ ScreenSh sh;
    int b = blockIdx.x;
    for (int i = threadIdx.x; i < NF; i += 256) contrib[i] = 0.f;
    for (int d = threadIdx.x; d < ND; d += 256) iar[d] = ia[(size_t)b * ND + d];
    __syncthreads();

    int wid = threadIdx.x >> 5, lane = threadIdx.x & 31;
    for (int t = wid; t < NK; t += 8) {
        float v = g_upv[b * NK + t];
        int j = g_upi[b * NK + t];
        if (v != 0.f) {
            int e0 = g_offs[j], e1 = g_offs[j + 1];
            for (int e = e0 + lane; e < e1; e += 32)
                atomicAdd(&contrib[g_invr[e]], v * g_invw[e]);
        }
    }
    __syncthreads();
    float ls = lnscale[b];
    const float* arow = act + (size_t)b * NF;
    for (int i = threadIdx.x; i < NF; i += 256)
        vals[i] = __fdiv_rn(arow[i] + contrib[i] + g_cvu[i], ls) + bencd[i] - g_cvd[i];
    __syncthreads();

    screen_collect(vals, hist, cand, &sh);

    if (threadIdx.x < NCAND) {
        int r = cand[threadIdx.x];
        float s = seqdot(Wed + (size_t)r * ND, iar);
        cex[threadIdx.x] = __fdiv_rn(s + contrib[r] + g_cvu[r], ls) + bencd[r] - g_cvd[r];
    }
    __syncthreads();

    if (threadIdx.x < NCAND) {
        float v = cex[threadIdx.x];
        int rank = 0;
        for (int u = 0; u < NCAND; u++) {
            float w = cex[u];
            rank += (w > v) || (w == v && u < (int)threadIdx.x);
        }
        if (rank < NK) { oidx[b * NK + rank] = cand[threadIdx.x]; oval[b * NK + rank] = v; }
    }
}

// ---------------- sparse decode (fp32, float4) ----------------
__global__ __launch_bounds__(192)
void k_decode(const float* __restrict__ bdd, float* __restrict__ out) {
    __shared__ int sj[NK];
    __shared__ float sv[NK];
    int b = blockIdx.x;
    if (threadIdx.x < NK) {
        sj[threadIdx.x] = g_dni[b * NK + threadIdx.x];
        sv[threadIdx.x] = g_dnv[b * NK + threadIdx.x];
    }
    __syncthreads();
    int q = threadIdx.x;  // 0..191, one float4 each
    float4 acc = ((const float4*)bdd)[q];
#pragma unroll 4
    for (int t = 0; t < NK; t++) {
        float4 w = ((const float4*)(g_WddT + (size_t)sj[t] * ND))[q];
        float v = sv[t];
        acc.x = fmaf(v, w.x, acc.x);
        acc.y = fmaf(v, w.y, acc.y);
        acc.z = fmaf(v, w.z, acc.z);
        acc.w = fmaf(v, w.w, acc.w);
    }
    ((float4*)(out + (size_t)b * ND))[q] = acc;
}

// ---------------- launch ----------------
extern "C" void kernel_launch(void* const* d_in, const int* in_sizes, int n_in,
                              void* d_out, int out_size) {
    const float* initial_acts = (const float*)d_in[0];
    const float* x_up        = (const float*)d_in[1];
    const float* ln_scale    = (const float*)d_in[2];
    const float* W_enc_up    = (const float*)d_in[3];
    const float* b_enc_up    = (const float*)d_in[4];
    const float* b_dec_up    = (const float*)d_in[5];
    const float* W_dec_up    = (const float*)d_in[6];
    const float* W_enc_down  = (const float*)d_in[7];
    const float* b_enc_down  = (const float*)d_in[8];
    const float* b_dec_down  = (const float*)d_in[9];
    const float* W_dec_down  = (const float*)d_in[10];
    const void*  conn_raw    = d_in[11];

    void *pa, *pa2, *pWduT, *pWddT, *pui, *puv, *pdi, *pdv, *pxb, *piab, *pwub, *pweb;
    cudaGetSymbolAddress(&pa, g_act);
    cudaGetSymbolAddress(&pa2, g_act2);
    cudaGetSymbolAddress(&pWduT, g_WduT);
    cudaGetSymbolAddress(&pWddT, g_WddT);
    cudaGetSymbolAddress(&pui, g_upi);
    cudaGetSymbolAddress(&puv, g_upv);
    cudaGetSymbolAddress(&pdi, g_dni);
    cudaGetSymbolAddress(&pdv, g_dnv);
    cudaGetSymbolAddress(&pxb, g_xb);
    cudaGetSymbolAddress(&piab, g_iab);
    cudaGetSymbolAddress(&pwub, g_wub);
    cudaGetSymbolAddress(&pweb, g_web);
    float* act = (float*)pa;
    float* act2 = (float*)pa2;

    const int up_smem = (NF + 256 + ND + 2 * NCAND) * 4;
    const int dn_smem = (2 * NF + 256 + ND + 2 * NCAND) * 4;

    // one-time setup on the uncaptured correctness call
    static bool inited = false;
    static cudaStream_t sB, sC;
    static cudaEvent_t evFork, evB, evC, evG1;
    if (!inited) {
        cudaStreamCreateWithFlags(&sB, cudaStreamNonBlocking);
        cudaStreamCreateWithFlags(&sC, cudaStreamNonBlocking);
        cudaEventCreateWithFlags(&evFork, cudaEventDisableTiming);
        cudaEventCreateWithFlags(&evB, cudaEventDisableTiming);
        cudaEventCreateWithFlags(&evC, cudaEventDisableTiming);
        cudaEventCreateWithFlags(&evG1, cudaEventDisableTiming);
        cudaFuncSetAttribute(k_topk_up, cudaFuncAttributeMaxDynamicSharedMemorySize, up_smem);
        cudaFuncSetAttribute(k_down, cudaFuncAttributeMaxDynamicSharedMemorySize, dn_smem);
        cudaFuncSetAttribute(k_hmma<true, true>, cudaFuncAttributeMaxDynamicSharedMemorySize, HMMA_SMEM);
        cudaFuncSetAttribute(k_hmma<false, false>, cudaFuncAttributeMaxDynamicSharedMemorySize, HMMA_SMEM);
        inited = true;
    }

    // ---- fork ----
    cudaEventRecord(evFork, 0);
    cudaStreamWaitEvent(sB, evFork, 0);
    cudaStreamWaitEvent(sC, evFork, 0);

    // ---- chain B (sB): connections, transposes, vw, inverted index, cvec ----
    k_init<<<48, 256, 0, sB>>>();
    k_detect<<<(NF * NC / 2) / 256, 256, 0, sB>>>((const unsigned*)conn_raw);
    k_conv<<<(NF * NC) / 256, 256, 0, sB>>>((const int*)conn_raw);
    k_dedup<<<NF, NC, 0, sB>>>();
    k_cvec<<<NF / 8, 256, 0, sB>>>(W_enc_down, b_dec_up, b_dec_down);
    k_transpose<<<dim3(NF / 32, ND / 32), dim3(32, 8), 0, sB>>>(W_dec_up, (float*)pWduT, ND, NF);
    k_transpose<<<dim3(NF / 32, ND / 32), dim3(32, 8), 0, sB>>>(W_dec_down, (float*)pWddT, ND, NF);
    k_vw<<<NF, 256, 0, sB>>>(W_enc_down);
    k_hist<<<(NF * NC) / 256, 256, 0, sB>>>();
    k_scan<<<1, 1024, 0, sB>>>();
    k_fill<<<(NF * NC) / 256, 256, 0, sB>>>();
    cudaEventRecord(evB, sB);

    // ---- chain A (default stream): converts, GEMM1, topk_up ----
    k_tobf<<<(NB * ND) / 256, 256>>>(x_up, b_dec_up, (__nv_bfloat16*)pxb);
    k_tobf<<<(NF * ND) / 256, 256>>>(W_enc_up, nullptr, (__nv_bfloat16*)pwub);
    k_tobf<<<(NB * ND) / 256, 256>>>(initial_acts, nullptr, (__nv_bfloat16*)piab);
    k_tobf<<<(NF * ND) / 256, 256>>>(W_enc_down, nullptr, (__nv_bfloat16*)pweb);
    k_hmma<true, true><<<dim3(NF / 128, NB / 128), 256, HMMA_SMEM>>>(
        (const __nv_bfloat16*)pxb, (const __nv_bfloat16*)pwub, b_enc_up, act, NF);
    cudaEventRecord(evG1, 0);
    k_topk_up<<<NB, 256, up_smem>>>(act, x_up, b_dec_up, W_enc_up, b_enc_up,
                                    (int*)pui, (float*)puv);

    // ---- chain C (sC): GEMM2 into act2, overlapping topk_up ----
    cudaStreamWaitEvent(sC, evG1, 0);
    k_hmma<false, false><<<dim3(NF / 128, NB / 128), 256, HMMA_SMEM, sC>>>(
        (const __nv_bfloat16*)piab, (const __nv_bfloat16*)pweb, nullptr, act2, NF);
    cudaEventRecord(evC, sC);

    // ---- join on default stream ----
    cudaStreamWaitEvent(0, evB, 0);
    cudaStreamWaitEvent(0, evC, 0);
    k_down<<<NB, 256, dn_smem>>>(act2, initial_acts, W_enc_down, ln_scale, b_enc_down,
                                 (int*)pdi, (float*)pdv);
    k_decode<<<NB, 192>>>(b_dec_down, (float*)d_out);
}

// round 8
// speedup vs baseline: 1.5409x; 1.0472x over previous
#include <cuda_runtime.h>
#include <cuda_bf16.h>
#include <cstdint>

#define NB 4096
#define ND 768
#define NF 12288
#define NC 256
#define NK 64
#define TARGETC 128
#define CAPC 384

// HMMA GEMM tiling (plain bf16, single product)
#define KC 32
#define SMPITCH 80
#define HALF_BYTES (128 * SMPITCH)   // 10240
#define STAGE (2 * HALF_BYTES)       // A + B
#define HMMA_SMEM (2 * STAGE)        // 40960

#define VW_SMEM ((ND / 4) * 16 + 8 * 2 * (ND / 4) * 16)  // 52224

// ---------------- device scratch ----------------
__device__ __nv_bfloat16 g_act[(size_t)NB * NF];
__device__ __nv_bfloat16 g_act2[(size_t)NB * NF];
__device__ float g_WduT[(size_t)NF * ND];     // fp32 [F_up, D] for vw gather
__device__ float g_WddT[(size_t)NF * ND];     // fp32 [F_down, D] for decode
__device__ __nv_bfloat16 g_xb[NB * ND];
__device__ __nv_bfloat16 g_iab[NB * ND];
__device__ __nv_bfloat16 g_wub[(size_t)NF * ND];
__device__ __nv_bfloat16 g_web[(size_t)NF * ND];
__device__ float g_vw[NF * NC];
__device__ float g_cvu[NF];
__device__ float g_cvd[NF];
__device__ int   g_upi[NB * NK];
__device__ float g_upv[NB * NK];
__device__ int   g_dni[NB * NK];
__device__ float g_dnv[NB * NK];
__device__ int   g_conn[NF * NC];
__device__ int   g_flag;
__device__ int   g_counts[NF];
__device__ int   g_offs[NF + 1];
__device__ int   g_cursor[NF];
__device__ int   g_invr[NF * NC];
__device__ float g_invw[NF * NC];

// ---------------- PTX helpers ----------------
__device__ __forceinline__ uint32_t smem_u32(const void* p) {
    uint32_t a;
    asm("{ .reg .u64 t; cvta.to.shared.u64 t, %1; cvt.u32.u64 %0, t; }" : "=r"(a) : "l"(p));
    return a;
}
__device__ __forceinline__ void cpasync16(uint32_t s, const void* g) {
    asm volatile("cp.async.cg.shared.global [%0], [%1], 16;" :: "r"(s), "l"(g));
}
__device__ __forceinline__ void ldmx4(uint32_t* r, uint32_t addr) {
    asm volatile("ldmatrix.sync.aligned.m8n8.x4.shared.b16 {%0,%1,%2,%3}, [%4];"
                 : "=r"(r[0]), "=r"(r[1]), "=r"(r[2]), "=r"(r[3]) : "r"(addr));
}
__device__ __forceinline__ void mma16816(float* c, const uint32_t* a, uint32_t b0, uint32_t b1) {
    asm volatile(
        "mma.sync.aligned.m16n8k16.row.col.f32.bf16.bf16.f32 "
        "{%0,%1,%2,%3}, {%4,%5,%6,%7}, {%8,%9}, {%0,%1,%2,%3};"
        : "+f"(c[0]), "+f"(c[1]), "+f"(c[2]), "+f"(c[3])
        : "r"(a[0]), "r"(a[1]), "r"(a[2]), "r"(a[3]), "r"(b0), "r"(b1));
}

__device__ __forceinline__ unsigned fkey(float x) {
    unsigned u = __float_as_uint(x);
    return (u & 0x80000000u) ? ~u : (u | 0x80000000u);
}

// Exact sequential ascending-k dot (R1-identical arithmetic for rescore)
__device__ __forceinline__ float seqdot(const float* __restrict__ w, const float* xr) {
    const float4* w4 = (const float4*)w;
    const float4* x4 = (const float4*)xr;
    float acc = 0.f;
#pragma unroll 4
    for (int k = 0; k < ND / 4; k++) {
        float4 wv = w4[k];
        float4 xv = x4[k];
        acc = fmaf(xv.x, wv.x, acc);
        acc = fmaf(xv.y, wv.y, acc);
        acc = fmaf(xv.z, wv.z, acc);
        acc = fmaf(xv.w, wv.w, acc);
    }
    return acc;
}

// ---------------- setup kernels ----------------
__global__ void k_init() {
    int i = blockIdx.x * 256 + threadIdx.x;
    if (i < NF) { g_counts[i] = 0; g_cursor[i] = 0; }
    if (i == 0) g_flag = 0;
}

__global__ void k_detect(const unsigned* __restrict__ raw) {
    int i = blockIdx.x * 256 + threadIdx.x;
    bool nz = (raw[2 * i + 1] != 0u);
    if (__syncthreads_or(nz) && threadIdx.x == 0) atomicOr(&g_flag, 1);
}

__global__ void k_conv(const int* __restrict__ raw) {
    int i = blockIdx.x * 256 + threadIdx.x;
    g_conn[i] = g_flag ? raw[i] : raw[2 * i];
}

__global__ void k_dedup() {
    __shared__ unsigned bm[NF / 32];
    int r = blockIdx.x;
    for (int i = threadIdx.x; i < NF / 32; i += NC) bm[i] = 0;
    __syncthreads();
    int c = threadIdx.x;
    int j = g_conn[r * NC + c];
    unsigned bit = 1u << (j & 31);
    unsigned old = atomicOr(&bm[j >> 5], bit);
    if (old & bit) g_conn[r * NC + c] = -1;
}

__global__ void k_tobf(const float* __restrict__ in, const float* __restrict__ sub,
                       __nv_bfloat16* __restrict__ out) {
    int i = blockIdx.x * 256 + threadIdx.x;
    float x = in[i];
    if (sub) x -= sub[i % ND];
    out[i] = __float2bfloat16(x);
}

__global__ void k_cvec(const float* __restrict__ Wed, const float* __restrict__ bdu,
                       const float* __restrict__ bdd) {
    int r = blockIdx.x * 8 + (threadIdx.x >> 5);
    int lane = threadIdx.x & 31;
    const float* wr = Wed + (size_t)r * ND;
    float s1 = 0.f, s2 = 0.f;
    for (int d = lane; d < ND; d += 32) { float w = wr[d]; s1 += w * bdu[d]; s2 += w * bdd[d]; }
    for (int o = 16; o; o >>= 1) { s1 += __shfl_xor_sync(~0u, s1, o); s2 += __shfl_xor_sync(~0u, s2, o); }
    if (!lane) { g_cvu[r] = s1; g_cvd[r] = s2; }
}

__global__ void k_transpose(const float* __restrict__ in, float* __restrict__ out,
                            int rows, int cols) {
    __shared__ float tile[32][33];
    int c0 = blockIdx.x * 32, r0 = blockIdx.y * 32;
    int x = threadIdx.x, y = threadIdx.y;
    for (int i = 0; i < 32; i += 8)
        tile[y + i][x] = in[(size_t)(r0 + y + i) * cols + c0 + x];
    __syncthreads();
    for (int i = 0; i < 32; i += 8)
        out[(size_t)(c0 + y + i) * rows + r0 + x] = tile[x][y + i];
}

// ---------------- plain-bf16 HMMA GEMM: C[M,N] = A[M,K] * B[N,K]^T, bf16 out ----------------
template <bool RELU, bool BIAS>
__global__ __launch_bounds__(256)
void k_hmma(const __nv_bfloat16* __restrict__ A, const __nv_bfloat16* __restrict__ B,
            const float* __restrict__ bias, __nv_bfloat16* __restrict__ C, int N) {
    extern __shared__ unsigned char sm[];
    uint32_t sb = smem_u32(sm);
    int tid = threadIdx.x, wid = tid >> 5, lane = tid & 31;
    int bm = blockIdx.y * 128, bn = blockIdx.x * 128;
    int wm = (wid >> 2) * 64, wn = (wid & 3) * 32;

    const char* gA = (const char*)(A + (size_t)bm * ND);
    const char* gB = (const char*)(B + (size_t)bn * ND);

    float acc[4][4][4];
#pragma unroll
    for (int mi = 0; mi < 4; mi++)
#pragma unroll
        for (int ni = 0; ni < 4; ni++)
#pragma unroll
            for (int q = 0; q < 4; q++) acc[mi][ni][q] = 0.f;

    int l_row = tid >> 1;
    int l_q2 = (tid & 1) * 2;
    auto load_stage = [&](int buf, int kc) {
        uint32_t s0 = sb + buf * STAGE;
        const char* srcs[2] = { gA + kc * (KC * 2), gB + kc * (KC * 2) };
#pragma unroll
        for (int h = 0; h < 2; h++) {
            uint32_t so = s0 + h * HALF_BYTES + l_row * SMPITCH + l_q2 * 16;
            const char* gp = srcs[h] + (size_t)l_row * (ND * 2) + l_q2 * 16;
            cpasync16(so, gp);
            cpasync16(so + 16, gp + 16);
        }
        asm volatile("cp.async.commit_group;" ::: "memory");
    };

    load_stage(0, 0);

    const int NCH = ND / KC;  // 24
    for (int i = 0; i < NCH; i++) {
        if (i + 1 < NCH) {
            load_stage((i + 1) & 1, i + 1);
            asm volatile("cp.async.wait_group 1;" ::: "memory");
        } else {
            asm volatile("cp.async.wait_group 0;" ::: "memory");
        }
        __syncthreads();

        uint32_t s0 = sb + (i & 1) * STAGE;
        uint32_t aB = s0, bB = s0 + HALF_BYTES;
        int lrow = lane & 15;
        int lcol = (lane >> 4) * 8;
#pragma unroll
        for (int ks = 0; ks < 2; ks++) {
            uint32_t aoff = (uint32_t)((wm + lrow) * SMPITCH + (lcol + ks * 16) * 2);
            uint32_t boff = (uint32_t)((wn + lrow) * SMPITCH + (lcol + ks * 16) * 2);
            uint32_t a[4][4], b[2][4];
#pragma unroll
            for (int mi = 0; mi < 4; mi++) ldmx4(a[mi], aB + aoff + mi * 16 * SMPITCH);
#pragma unroll
            for (int nj = 0; nj < 2; nj++) ldmx4(b[nj], bB + boff + nj * 16 * SMPITCH);
#pragma unroll
            for (int mi = 0; mi < 4; mi++)
#pragma unroll
                for (int ni = 0; ni < 4; ni++) {
                    int nj = ni >> 1, o = ni & 1;
                    mma16816(acc[mi][ni], a[mi], b[nj][o], b[nj][o + 2]);
                }
        }
        __syncthreads();
    }

    int gid = lane >> 2, qc = (lane & 3) * 2;
#pragma unroll
    for (int mi = 0; mi < 4; mi++)
#pragma unroll
        for (int ni = 0; ni < 4; ni++) {
            int col = bn + wn + ni * 8 + qc;
            float bx = 0.f, by = 0.f;
            if (BIAS) { float2 b2 = *(const float2*)&bias[col]; bx = b2.x; by = b2.y; }
#pragma unroll
            for (int h = 0; h < 2; h++) {
                int row = bm + wm + mi * 16 + gid + h * 8;
                float x = acc[mi][ni][2 * h] + bx;
                float y = acc[mi][ni][2 * h + 1] + by;
                if (RELU) { x = fmaxf(x, 0.f); y = fmaxf(y, 0.f); }
                __nv_bfloat162 p = __floats2bfloat162_rn(x, y);
                *(__nv_bfloat162*)&C[(size_t)row * N + col] = p;
            }
        }
}

// ---------------- adaptive radix screen: collect >= top-TARGETC candidates ----------------
struct ScreenSh { int bin, above, bcnt, ca, ce; };

__device__ __forceinline__ int screen_collect(const float* vals, int* hist, int* cand,
                                              ScreenSh* sh) {
    unsigned prefix = 0;
    int need = TARGETC, tot = 0, binCount = 0, shift = 24;
    for (int lev = 0; lev < 4; lev++) {
        shift = 24 - 8 * lev;
        hist[threadIdx.x] = 0;
        __syncthreads();
        for (int i = threadIdx.x; i < NF; i += 256) {
            unsigned k = fkey(vals[i]);
            if (lev == 0 || (k >> (shift + 8)) == prefix)
                atomicAdd(&hist[(k >> shift) & 255], 1);
        }
        __syncthreads();
        if (threadIdx.x == 0) {
            int acc = 0, bb = 255;
            for (;;) { acc += hist[bb]; if (acc >= need || bb == 0) break; bb--; }
            sh->bin = bb;
            sh->above = acc - hist[bb];
            sh->bcnt = hist[bb];
        }
        __syncthreads();
        prefix = (prefix << 8) | (unsigned)sh->bin;
        need -= sh->above;
        tot += sh->above;
        binCount = sh->bcnt;
        __syncthreads();
        if (lev >= 1 && tot + binCount <= CAPC) break;
    }
    if (threadIdx.x == 0) { sh->ca = 0; sh->ce = 0; }
    __syncthreads();
    for (int i = threadIdx.x; i < NF; i += 256) {
        unsigned kp = fkey(vals[i]) >> shift;
        if (kp > prefix) {
            int p = atomicAdd(&sh->ca, 1);
            cand[p] = i;
        } else if (kp == prefix) {
            int p = tot + atomicAdd(&sh->ce, 1);
            if (p < CAPC) cand[p] = i;
        }
    }
    __syncthreads();
    int M = tot + binCount;
    return (M > CAPC) ? CAPC : M;
}

// ---------------- upstream: screen + exact sequential rescore + top-64 ----------------
__global__ __launch_bounds__(256)
void k_topk_up(const __nv_bfloat16* __restrict__ act, const float* __restrict__ x_up,
               const float* __restrict__ bdu, const float* __restrict__ Wenc,
               const float* __restrict__ benc,
               int* __restrict__ oidx, float* __restrict__ oval) {
    extern __shared__ unsigned char smraw[];
    float* vals = (float*)smraw;                       // NF
    int* hist = (int*)(vals + NF);                     // 256
    float* xr = (float*)(hist + 256);                  // ND
    int* cand = (int*)(xr + ND);                       // CAPC
    float* cex = (float*)(cand + CAPC);                // CAPC
    __shared__ ScreenSh sh;
    int b = blockIdx.x;
    const __nv_bfloat162* row2 = (const __nv_bfloat162*)(act + (size_t)b * NF);
    for (int i = threadIdx.x; i < NF / 2; i += 256) {
        float2 f = __bfloat1622float2(row2[i]);
        vals[2 * i] = f.x; vals[2 * i + 1] = f.y;
    }
    for (int d = threadIdx.x; d < ND; d += 256) xr[d] = x_up[(size_t)b * ND + d] - bdu[d];
    __syncthreads();

    int M = screen_collect(vals, hist, cand, &sh);

    for (int c = threadIdx.x; c < M; c += 256) {
        int j = cand[c];
        float s = seqdot(Wenc + (size_t)j * ND, xr);
        cex[c] = fmaxf(s + benc[j], 0.f);
    }
    __syncthreads();

    for (int idx = threadIdx.x; idx < M; idx += 256) {
        float v = cex[idx];
        int rank = 0;
        for (int u = 0; u < M; u++) {
            float w = cex[u];
            rank += (w > v) || (w == v && u < idx);
        }
        if (rank < NK) { oidx[b * NK + rank] = cand[idx]; oval[b * NK + rank] = v; }
    }
}

// ---------------- sampled virtual weights: cp.async streaming, fp32 ----------------
__global__ __launch_bounds__(256)
void k_vw(const float* __restrict__ Wed) {
    extern __shared__ unsigned char vsm[];
    float4* arow = (float4*)vsm;                       // ND/4
    float4* jall = (float4*)(vsm + (ND / 4) * 16);     // 8 warps x 2 bufs x ND/4
    int r = blockIdx.x;
    const float4* wr4 = (const float4*)(Wed + (size_t)r * ND);
    for (int d = threadIdx.x; d < ND / 4; d += 256) arow[d] = wr4[d];
    __syncthreads();
    int w = threadIdx.x >> 5, lane = threadIdx.x & 31;
    float4* jbuf[2] = { jall + (w * 2 + 0) * (ND / 4), jall + (w * 2 + 1) * (ND / 4) };
    uint32_t jb[2] = { smem_u32(jbuf[0]), smem_u32(jbuf[1]) };

    int jcur = g_conn[r * NC + w];
    if (jcur >= 0) {
        const char* src = (const char*)(g_WduT + (size_t)jcur * ND);
#pragma unroll
        for (int q = 0; q < 6; q++)
            cpasync16(jb[0] + (q * 32 + lane) * 16, src + (q * 32 + lane) * 16);
    }
    asm volatile("cp.async.commit_group;" ::: "memory");

    for (int it = 0; it < 32; it++) {
        int buf = it & 1;
        int jn = -1;
        if (it + 1 < 32) {
            jn = g_conn[r * NC + w + (it + 1) * 8];
            if (jn >= 0) {
                const char* src = (const char*)(g_WduT + (size_t)jn * ND);
#pragma unroll
                for (int q = 0; q < 6; q++)
                    cpasync16(jb[buf ^ 1] + (q * 32 + lane) * 16, src + (q * 32 + lane) * 16);
            }
        }
        asm volatile("cp.async.commit_group;" ::: "memory");
        asm volatile("cp.async.wait_group 1;" ::: "memory");
        if (jcur >= 0) {
            float s = 0.f;
            const float4* jr = jbuf[buf];
#pragma unroll
            for (int q = 0; q < 6; q++) {
                float4 a = arow[q * 32 + lane];
                float4 v = jr[q * 32 + lane];
                s += a.x * v.x + a.y * v.y + a.z * v.z + a.w * v.w;
            }
            for (int o = 16; o; o >>= 1) s += __shfl_xor_sync(~0u, s, o);
            if (!lane) g_vw[r * NC + w + it * 8] = s;
        }
        jcur = jn;
    }
}

// ---------------- inverted connection index ----------------
__global__ void k_hist() {
    int i = blockIdx.x * 256 + threadIdx.x;
    int j = g_conn[i];
    if (j >= 0) atomicAdd(&g_counts[j], 1);
}

__global__ void k_scan() {
    __shared__ int part[1024];
    int t = threadIdx.x;
    int base = t * 12;
    int loc[12], s = 0;
    for (int i = 0; i < 12; i++) { loc[i] = s; s += g_counts[base + i]; }
    part[t] = s;
    __syncthreads();
    for (int o = 1; o < 1024; o <<= 1) {
        int v = (t >= o) ? part[t - o] : 0;
        __syncthreads();
        part[t] += v;
        __syncthreads();
    }
    int excl = part[t] - s;
    for (int i = 0; i < 12; i++) g_offs[base + i] = excl + loc[i];
    if (t == 1023) g_offs[NF] = part[1023];
}

__global__ void k_fill() {
    int i = blockIdx.x * 256 + threadIdx.x;
    int j = g_conn[i];
    if (j >= 0) {
        int p = atomicAdd(&g_cursor[j], 1);
        int e = g_offs[j] + p;
        g_invr[e] = i >> 8;
        g_invw[e] = g_vw[i];
    }
}

// ---------------- down: scatter + screen + exact rescore + top-64 ----------------
__global__ __launch_bounds__(256)
void k_down(const __nv_bfloat16* __restrict__ act, const float* __restrict__ ia,
            const float* __restrict__ Wed, const float* __restrict__ lnscale,
            const float* __restrict__ bencd,
            int* __restrict__ oidx, float* __restrict__ oval) {
    extern __shared__ unsigned char smraw[];
    float* contrib = (float*)smraw;                    // NF
    float* vals = contrib + NF;                        // NF
    int* hist = (int*)(vals + NF);                     // 256
    float* iar = (float*)(hist + 256);                 // ND
    int* cand = (int*)(iar + ND);                      // CAPC
    float* cex = (float*)(cand + CAPC);                // CAPC
    __shared__ ScreenSh sh;
    int b = blockIdx.x;
    for (int i = threadIdx.x; i < NF; i += 256) contrib[i] = 0.f;
    for (int d = threadIdx.x; d < ND; d += 256) iar[d] = ia[(size_t)b * ND + d];
    __syncthreads();

    int wid = threadIdx.x >> 5, lane = threadIdx.x & 31;
    for (int t = wid; t < NK; t += 8) {
        float v = g_upv[b * NK + t];
        int j = g_upi[b * NK + t];
        if (v != 0.f) {
            int e0 = g_offs[j], e1 = g_offs[j + 1];
            for (int e = e0 + lane; e < e1; e += 32)
                atomicAdd(&contrib[g_invr[e]], v * g_invw[e]);
        }
    }
    __syncthreads();
    float ls = lnscale[b];
    const __nv_bfloat162* arow2 = (const __nv_bfloat162*)(act + (size_t)b * NF);
    for (int i = threadIdx.x; i < NF / 2; i += 256) {
        float2 f = __bfloat1622float2(arow2[i]);
        vals[2 * i]     = __fdiv_rn(f.x + contrib[2 * i] + g_cvu[2 * i], ls) + bencd[2 * i] - g_cvd[2 * i];
        vals[2 * i + 1] = __fdiv_rn(f.y + contrib[2 * i + 1] + g_cvu[2 * i + 1], ls) + bencd[2 * i + 1] - g_cvd[2 * i + 1];
    }
    __syncthreads();

    int M = screen_collect(vals, hist, cand, &sh);

    for (int c = threadIdx.x; c < M; c += 256) {
        int r = cand[c];
        float s = seqdot(Wed + (size_t)r * ND, iar);
        cex[c] = __fdiv_rn(s + contrib[r] + g_cvu[r], ls) + bencd[r] - g_cvd[r];
    }
    __syncthreads();

    for (int idx = threadIdx.x; idx < M; idx += 256) {
        float v = cex[idx];
        int rank = 0;
        for (int u = 0; u < M; u++) {
            float w = cex[u];
            rank += (w > v) || (w == v && u < idx);
        }
        if (rank < NK) { oidx[b * NK + rank] = cand[idx]; oval[b * NK + rank] = v; }
    }
}

// ---------------- sparse decode (fp32, float4) ----------------
__global__ __launch_bounds__(192)
void k_decode(const float* __restrict__ bdd, float* __restrict__ out) {
    __shared__ int sj[NK];
    __shared__ float sv[NK];
    int b = blockIdx.x;
    if (threadIdx.x < NK) {
        sj[threadIdx.x] = g_dni[b * NK + threadIdx.x];
        sv[threadIdx.x] = g_dnv[b * NK + threadIdx.x];
    }
    __syncthreads();
    int q = threadIdx.x;
    float4 acc = ((const float4*)bdd)[q];
#pragma unroll 4
    for (int t = 0; t < NK; t++) {
        float4 w = ((const float4*)(g_WddT + (size_t)sj[t] * ND))[q];
        float v = sv[t];
        acc.x = fmaf(v, w.x, acc.x);
        acc.y = fmaf(v, w.y, acc.y);
        acc.z = fmaf(v, w.z, acc.z);
        acc.w = fmaf(v, w.w, acc.w);
    }
    ((float4*)(out + (size_t)b * ND))[q] = acc;
}

// ---------------- launch ----------------
extern "C" void kernel_launch(void* const* d_in, const int* in_sizes, int n_in,
                              void* d_out, int out_size) {
    const float* initial_acts = (const float*)d_in[0];
    const float* x_up        = (const float*)d_in[1];
    const float* ln_scale    = (const float*)d_in[2];
    const float* W_enc_up    = (const float*)d_in[3];
    const float* b_enc_up    = (const float*)d_in[4];
    const float* b_dec_up    = (const float*)d_in[5];
    const float* W_dec_up    = (const float*)d_in[6];
    const float* W_enc_down  = (const float*)d_in[7];
    const float* b_enc_down  = (const float*)d_in[8];
    const float* b_dec_down  = (const float*)d_in[9];
    const float* W_dec_down  = (const float*)d_in[10];
    const void*  conn_raw    = d_in[11];

    void *pa, *pa2, *pWduT, *pWddT, *pui, *puv, *pdi, *pdv, *pxb, *piab, *pwub, *pweb;
    cudaGetSymbolAddress(&pa, g_act);
    cudaGetSymbolAddress(&pa2, g_act2);
    cudaGetSymbolAddress(&pWduT, g_WduT);
    cudaGetSymbolAddress(&pWddT, g_WddT);
    cudaGetSymbolAddress(&pui, g_upi);
    cudaGetSymbolAddress(&puv, g_upv);
    cudaGetSymbolAddress(&pdi, g_dni);
    cudaGetSymbolAddress(&pdv, g_dnv);
    cudaGetSymbolAddress(&pxb, g_xb);
    cudaGetSymbolAddress(&piab, g_iab);
    cudaGetSymbolAddress(&pwub, g_wub);
    cudaGetSymbolAddress(&pweb, g_web);
    __nv_bfloat16* act = (__nv_bfloat16*)pa;
    __nv_bfloat16* act2 = (__nv_bfloat16*)pa2;

    const int up_smem = (NF + 256 + ND + 2 * CAPC) * 4;            // 56320
    const int dn_smem = (2 * NF + 256 + ND + 2 * CAPC) * 4;        // 105472

    static bool inited = false;
    static cudaStream_t sB, sC;
    static cudaEvent_t evFork, evB, evC, evG1;
    if (!inited) {
        cudaStreamCreateWithFlags(&sB, cudaStreamNonBlocking);
        cudaStreamCreateWithFlags(&sC, cudaStreamNonBlocking);
        cudaEventCreateWithFlags(&evFork, cudaEventDisableTiming);
        cudaEventCreateWithFlags(&evB, cudaEventDisableTiming);
        cudaEventCreateWithFlags(&evC, cudaEventDisableTiming);
        cudaEventCreateWithFlags(&evG1, cudaEventDisableTiming);
        cudaFuncSetAttribute(k_topk_up, cudaFuncAttributeMaxDynamicSharedMemorySize, up_smem);
        cudaFuncSetAttribute(k_down, cudaFuncAttributeMaxDynamicSharedMemorySize, dn_smem);
        cudaFuncSetAttribute(k_vw, cudaFuncAttributeMaxDynamicSharedMemorySize, VW_SMEM);
        cudaFuncSetAttribute(k_hmma<true, true>, cudaFuncAttributeMaxDynamicSharedMemorySize, HMMA_SMEM);
        cudaFuncSetAttribute(k_hmma<false, false>, cudaFuncAttributeMaxDynamicSharedMemorySize, HMMA_SMEM);
        inited = true;
    }

    // ---- fork ----
    cudaEventRecord(evFork, 0);
    cudaStreamWaitEvent(sB, evFork, 0);
    cudaStreamWaitEvent(sC, evFork, 0);

    // ---- chain B (sB): connections -> WduT transpose -> vw -> inverted index ----
    k_init<<<48, 256, 0, sB>>>();
    k_detect<<<(NF * NC / 2) / 256, 256, 0, sB>>>((const unsigned*)conn_raw);
    k_conv<<<(NF * NC) / 256, 256, 0, sB>>>((const int*)conn_raw);
    k_dedup<<<NF, NC, 0, sB>>>();
    k_transpose<<<dim3(NF / 32, ND / 32), dim3(32, 8), 0, sB>>>(W_dec_up, (float*)pWduT, ND, NF);
    k_vw<<<NF, 256, VW_SMEM, sB>>>(W_enc_down);
    k_hist<<<(NF * NC) / 256, 256, 0, sB>>>();
    k_scan<<<1, 1024, 0, sB>>>();
    k_fill<<<(NF * NC) / 256, 256, 0, sB>>>();
    k_cvec<<<NF / 8, 256, 0, sB>>>(W_enc_down, b_dec_up, b_dec_down);
    k_transpose<<<dim3(NF / 32, ND / 32), dim3(32, 8), 0, sB>>>(W_dec_down, (float*)pWddT, ND, NF);
    cudaEventRecord(evB, sB);

    // ---- chain A (default): converts for GEMM1, GEMM1, topk_up ----
    k_tobf<<<(NB * ND) / 256, 256>>>(x_up, b_dec_up, (__nv_bfloat16*)pxb);
    k_tobf<<<(NF * ND) / 256, 256>>>(W_enc_up, nullptr, (__nv_bfloat16*)pwub);
    k_hmma<true, true><<<dim3(NF / 128, NB / 128), 256, HMMA_SMEM>>>(
        (const __nv_bfloat16*)pxb, (const __nv_bfloat16*)pwub, b_enc_up, act, NF);
    cudaEventRecord(evG1, 0);
    k_topk_up<<<NB, 256, up_smem>>>(act, x_up, b_dec_up, W_enc_up, b_enc_up,
                                    (int*)pui, (float*)puv);

    // ---- chain C (sC): converts for GEMM2, then GEMM2 overlapping topk_up ----
    k_tobf<<<(NB * ND) / 256, 256, 0, sC>>>(initial_acts, nullptr, (__nv_bfloat16*)piab);
    k_tobf<<<(NF * ND) / 256, 256, 0, sC>>>(W_enc_down, nullptr, (__nv_bfloat16*)pweb);
    cudaStreamWaitEvent(sC, evG1, 0);
    k_hmma<false, false><<<dim3(NF / 128, NB / 128), 256, HMMA_SMEM, sC>>>(
        (const __nv_bfloat16*)piab, (const __nv_bfloat16*)pweb, nullptr, act2, NF);
    cudaEventRecord(evC, sC);

    // ---- join ----
    cudaStreamWaitEvent(0, evB, 0);
    cudaStreamWaitEvent(0, evC, 0);
    k_down<<<NB, 256, dn_smem>>>(act2, initial_acts, W_enc_down, ln_scale, b_enc_down,
                                 (int*)pdi, (float*)pdv);
    k_decode<<<NB, 192>>>(b_dec_down, (float*)d_out);
}